// round 1
// baseline (speedup 1.0000x reference)
#include <cuda_runtime.h>
#include <cstdint>

// Instant-NGP HashGrid encode: N=1048576 points, 16 levels, 2 feats/level,
// T = 2^19 entries/level, trilinear interp of 8 hashed corners.
//
// res_l = floor(16 * 1.4472692012786865^l) computed in f32 (matching jnp):
//   {16,23,33,48,70,101,147,212,307,445,645,933,1351,1955,2830,4095}
// (l=15: scale_f32^15 = 255.99990 < 256 -> 4095, NOT 4096.)

#define N_POINTS 1048576
#define N_LEVELS 16
#define LOG2_T   19
#define T_MASK   ((1u << LOG2_T) - 1u)
#define PRIME_Y  2654435761u
#define PRIME_Z  805459861u

__constant__ float c_res[N_LEVELS] = {
    16.f, 23.f, 33.f, 48.f, 70.f, 101.f, 147.f, 212.f,
    307.f, 445.f, 645.f, 933.f, 1351.f, 1955.f, 2830.f, 4095.f
};

__global__ __launch_bounds__(256)
void hashgrid_encode_kernel(const float* __restrict__ x,
                            const float2* __restrict__ table,
                            float2* __restrict__ out)
{
    const int tid = blockIdx.x * blockDim.x + threadIdx.x;  // [0, N*16)
    const int n = tid >> 4;      // point index
    const int l = tid & 15;      // level index

    const float res = c_res[l];

    // 16 threads share each point's coords -> L1 broadcast, negligible traffic.
    const float px = __ldg(x + 3 * n + 0);
    const float py = __ldg(x + 3 * n + 1);
    const float pz = __ldg(x + 3 * n + 2);

    // f32 math identical to reference: pos = x*res; p0 = floor(pos); frac = pos-p0
    const float fx = px * res, fy = py * res, fz = pz * res;
    const float x0 = floorf(fx), y0 = floorf(fy), z0 = floorf(fz);
    const float tx = fx - x0, ty = fy - y0, tz = fz - z0;

    const uint32_t ix = (uint32_t)x0, iy = (uint32_t)y0, iz = (uint32_t)z0;

    // Hash components: (v + c)*P = v*P + c*P  (uint32 wrap, matches jnp.uint32)
    const uint32_t ax0 = ix;                 // prime for dim0 is 1
    const uint32_t ax1 = ix + 1u;
    const uint32_t by0 = iy * PRIME_Y;
    const uint32_t by1 = by0 + PRIME_Y;
    const uint32_t cz0 = iz * PRIME_Z;
    const uint32_t cz1 = cz0 + PRIME_Z;

    const float2* __restrict__ tbl = table + ((size_t)l << LOG2_T);

    // Corner c: x-bit = c&1, y-bit = (c>>1)&1, z-bit = (c>>2)&1.
    // Issue all 8 gathers up front -> MLP = 8.
    const float2 v0 = __ldg(tbl + ((ax0 ^ by0 ^ cz0) & T_MASK));  // 000
    const float2 v1 = __ldg(tbl + ((ax1 ^ by0 ^ cz0) & T_MASK));  // 100
    const float2 v2 = __ldg(tbl + ((ax0 ^ by1 ^ cz0) & T_MASK));  // 010
    const float2 v3 = __ldg(tbl + ((ax1 ^ by1 ^ cz0) & T_MASK));  // 110
    const float2 v4 = __ldg(tbl + ((ax0 ^ by0 ^ cz1) & T_MASK));  // 001
    const float2 v5 = __ldg(tbl + ((ax1 ^ by0 ^ cz1) & T_MASK));  // 101
    const float2 v6 = __ldg(tbl + ((ax0 ^ by1 ^ cz1) & T_MASK));  // 011
    const float2 v7 = __ldg(tbl + ((ax1 ^ by1 ^ cz1) & T_MASK));  // 111

    // Trilinear weights
    const float ux = 1.0f - tx, uy = 1.0f - ty, uz = 1.0f - tz;
    const float w0 = ux * uy * uz;
    const float w1 = tx * uy * uz;
    const float w2 = ux * ty * uz;
    const float w3 = tx * ty * uz;
    const float w4 = ux * uy * tz;
    const float w5 = tx * uy * tz;
    const float w6 = ux * ty * tz;
    const float w7 = tx * ty * tz;

    float2 acc;
    acc.x = v0.x * w0 + v1.x * w1 + v2.x * w2 + v3.x * w3
          + v4.x * w4 + v5.x * w5 + v6.x * w6 + v7.x * w7;
    acc.y = v0.y * w0 + v1.y * w1 + v2.y * w2 + v3.y * w3
          + v4.y * w4 + v5.y * w5 + v6.y * w6 + v7.y * w7;

    // out[n][l*2 .. l*2+1] -> float2 at n*16 + l. Warp writes 256B contiguous.
    out[(size_t)n * N_LEVELS + l] = acc;
}

extern "C" void kernel_launch(void* const* d_in, const int* in_sizes, int n_in,
                              void* d_out, int out_size)
{
    const float*  x     = (const float*)d_in[0];
    const float2* table = (const float2*)d_in[1];
    float2*       out   = (float2*)d_out;

    const int total = N_POINTS * N_LEVELS;           // 16,777,216 threads
    const int block = 256;
    const int grid  = total / block;                 // 65,536 blocks
    hashgrid_encode_kernel<<<grid, block>>>(x, table, out);
}

// round 12
// speedup vs baseline: 1.0438x; 1.0438x over previous
#include <cuda_runtime.h>
#include <cstdint>

// Instant-NGP HashGrid encode: N=1048576 points, 16 levels, 2 feats/level,
// T = 2^19 entries/level, trilinear interp of 8 hashed corners.
//
// res_l = floor(16 * 1.4472692012786865^l) computed in f32 (matching jnp):
//   {16,23,33,48,70,101,147,212,307,445,645,933,1351,1955,2830,4095}
//
// R2-R11 (re-bench; broker timeouts): dim-0 hash prime is 1, so for EVEN ix
// the two x-corners of each (y,z) pair hash to adjacent entries {h, h^1} ->
// one 16B float4 load instead of two 8B float2 loads. Cuts L1tex wavefronts
// ~25% (L1 was the 91.6% binding pipe in R1).

#define N_POINTS 1048576
#define N_LEVELS 16
#define LOG2_T   19
#define T_MASK   ((1u << LOG2_T) - 1u)
#define PRIME_Y  2654435761u
#define PRIME_Z  805459861u

__constant__ float c_res[N_LEVELS] = {
    16.f, 23.f, 33.f, 48.f, 70.f, 101.f, 147.f, 212.f,
    307.f, 445.f, 645.f, 933.f, 1351.f, 1955.f, 2830.f, 4095.f
};

__global__ __launch_bounds__(256)
void hashgrid_encode_kernel(const float* __restrict__ x,
                            const float2* __restrict__ table,
                            float2* __restrict__ out)
{
    const int tid = blockIdx.x * blockDim.x + threadIdx.x;  // [0, N*16)
    const int n = tid >> 4;      // point index
    const int l = tid & 15;      // level index

    const float res = c_res[l];

    // 16 threads share each point's coords -> L1 broadcast, negligible traffic.
    const float px = __ldg(x + 3 * n + 0);
    const float py = __ldg(x + 3 * n + 1);
    const float pz = __ldg(x + 3 * n + 2);

    // f32 math identical to reference: pos = x*res; p0 = floor(pos); frac = pos-p0
    const float fx = px * res, fy = py * res, fz = pz * res;
    const float x0 = floorf(fx), y0 = floorf(fy), z0 = floorf(fz);
    const float tx = fx - x0, ty = fy - y0, tz = fz - z0;

    const uint32_t ix = (uint32_t)x0, iy = (uint32_t)y0, iz = (uint32_t)z0;

    // y/z hash components: (v + 1)*P = v*P + P (uint32 wrap, matches jnp)
    const uint32_t by0 = iy * PRIME_Y;
    const uint32_t by1 = by0 + PRIME_Y;
    const uint32_t cz0 = iz * PRIME_Z;
    const uint32_t cz1 = cz0 + PRIME_Z;

    // 4 (y,z) combos; i = ybit + 2*zbit
    uint32_t m0 = by0 ^ cz0;
    uint32_t m1 = by1 ^ cz0;
    uint32_t m2 = by0 ^ cz1;
    uint32_t m3 = by1 ^ cz1;

    const float2* __restrict__ tbl = table + ((size_t)l << LOG2_T);

    float2 va0, va1, va2, va3;   // x-bit = 0 corners
    float2 vb0, vb1, vb2, vb3;   // x-bit = 1 corners

    if ((ix & 1u) == 0u) {
        // Even ix: h(ix+1) = h(ix) ^ 1 -> pair lives in one 16B float4.
        const float4* __restrict__ tbl4 = (const float4*)tbl;
        #pragma unroll
        for (int i = 0; i < 4; i++) {
            const uint32_t m = (i == 0) ? m0 : (i == 1) ? m1 : (i == 2) ? m2 : m3;
            const uint32_t h0 = (ix ^ m) & T_MASK;
            const float4 q = __ldg(tbl4 + (h0 >> 1));
            float2 lo = make_float2(q.x, q.y);   // entry (h0 & ~1)
            float2 hi = make_float2(q.z, q.w);   // entry (h0 |  1)
            float2 a = (h0 & 1u) ? hi : lo;      // index h0   (x-bit 0)
            float2 b = (h0 & 1u) ? lo : hi;      // index h0^1 (x-bit 1)
            if (i == 0) { va0 = a; vb0 = b; }
            else if (i == 1) { va1 = a; vb1 = b; }
            else if (i == 2) { va2 = a; vb2 = b; }
            else { va3 = a; vb3 = b; }
        }
    } else {
        const uint32_t ax1 = ix + 1u;
        va0 = __ldg(tbl + ((ix  ^ m0) & T_MASK));
        vb0 = __ldg(tbl + ((ax1 ^ m0) & T_MASK));
        va1 = __ldg(tbl + ((ix  ^ m1) & T_MASK));
        vb1 = __ldg(tbl + ((ax1 ^ m1) & T_MASK));
        va2 = __ldg(tbl + ((ix  ^ m2) & T_MASK));
        vb2 = __ldg(tbl + ((ax1 ^ m2) & T_MASK));
        va3 = __ldg(tbl + ((ix  ^ m3) & T_MASK));
        vb3 = __ldg(tbl + ((ax1 ^ m3) & T_MASK));
    }

    // Trilinear weights. Corner c: x-bit = c&1, y-bit = (c>>1)&1, z-bit = (c>>2)&1.
    const float ux = 1.0f - tx, uy = 1.0f - ty, uz = 1.0f - tz;
    const float wy0z0 = uy * uz;
    const float wy1z0 = ty * uz;
    const float wy0z1 = uy * tz;
    const float wy1z1 = ty * tz;

    float2 acc;
    acc.x = (va0.x * ux + vb0.x * tx) * wy0z0
          + (va1.x * ux + vb1.x * tx) * wy1z0
          + (va2.x * ux + vb2.x * tx) * wy0z1
          + (va3.x * ux + vb3.x * tx) * wy1z1;
    acc.y = (va0.y * ux + vb0.y * tx) * wy0z0
          + (va1.y * ux + vb1.y * tx) * wy1z0
          + (va2.y * ux + vb2.y * tx) * wy0z1
          + (va3.y * ux + vb3.y * tx) * wy1z1;

    // out[n][l*2 .. l*2+1] -> float2 at n*16 + l. Warp writes 256B contiguous.
    out[(size_t)n * N_LEVELS + l] = acc;
}

extern "C" void kernel_launch(void* const* d_in, const int* in_sizes, int n_in,
                              void* d_out, int out_size)
{
    const float*  x     = (const float*)d_in[0];
    const float2* table = (const float2*)d_in[1];
    float2*       out   = (float2*)d_out;

    const int total = N_POINTS * N_LEVELS;           // 16,777,216 threads
    const int block = 256;
    const int grid  = total / block;                 // 65,536 blocks
    hashgrid_encode_kernel<<<grid, block>>>(x, table, out);
}